// round 1
// baseline (speedup 1.0000x reference)
#include <cuda_runtime.h>
#include <cuda_bf16.h>
#include <math_constants.h>

// Problem: for each of 8192 batch rows (64 ints, 0/1, popcount<=3), find its
// index in the canonical table of all popcount<=3 masks (ordered by popcount,
// then lexicographic combination order), and output W[idx] - logsumexp(W).
//
// The table row index is a closed-form combinatorial rank of the set bits,
// so the table input itself is never read.

#define N_BITS   64
#define K_MAX    3
#define BASE1    1                       // after the 1 zero row
#define BASE2    (1 + 64)                // 65
#define BASE3    (1 + 64 + 2016)         // 2081
#define C64_3    41664                   // C(64,3)

__device__ float g_lse;                  // logsumexp(W), written by lse_kernel

// ---------------------------------------------------------------------------
// Kernel 1: deterministic logsumexp over W (n = 43745). One block.
// ---------------------------------------------------------------------------
__global__ void lse_kernel(const float* __restrict__ W, int n) {
    __shared__ float sred[1024];
    const int t = threadIdx.x;

    // max pass
    float m = -CUDART_INF_F;
    for (int i = t; i < n; i += 1024) m = fmaxf(m, W[i]);
    sred[t] = m;
    __syncthreads();
    #pragma unroll
    for (int s = 512; s > 0; s >>= 1) {
        if (t < s) sred[t] = fmaxf(sred[t], sred[t + s]);
        __syncthreads();
    }
    const float gmax = sred[0];
    __syncthreads();

    // sum of exp pass (fixed strided order per thread -> deterministic)
    float acc = 0.0f;
    for (int i = t; i < n; i += 1024) acc += expf(W[i] - gmax);
    sred[t] = acc;
    __syncthreads();
    #pragma unroll
    for (int s = 512; s > 0; s >>= 1) {
        if (t < s) sred[t] += sred[t + s];
        __syncthreads();
    }
    if (t == 0) g_lse = gmax + logf(sred[0]);
}

// ---------------------------------------------------------------------------
// Kernel 2: one warp per batch row. Ballot the 64 ints into a 64-bit mask,
// combinatorially rank the set bits, gather W[idx] - lse.
// ---------------------------------------------------------------------------
__global__ void rank_gather_kernel(const int* __restrict__ x,
                                   const float* __restrict__ W,
                                   float* __restrict__ out,
                                   int batch) {
    const int gwarp = (blockIdx.x * blockDim.x + threadIdx.x) >> 5;
    const int lane  = threadIdx.x & 31;
    if (gwarp >= batch) return;

    const int* row = x + (long long)gwarp * N_BITS;
    // two fully-coalesced 128B transactions per warp
    const int v0 = row[lane];
    const int v1 = row[32 + lane];
    const unsigned lo = __ballot_sync(0xffffffffu, v0 != 0);
    const unsigned hi = __ballot_sync(0xffffffffu, v1 != 0);

    if (lane == 0) {
        unsigned long long m =
            (unsigned long long)lo | ((unsigned long long)hi << 32);
        const int c = __popcll(m);
        int idx;
        if (c == 0) {
            idx = 0;
        } else {
            const int p0 = __ffsll((long long)m) - 1;
            m &= m - 1;
            if (c == 1) {
                idx = BASE1 + p0;
            } else {
                const int p1 = __ffsll((long long)m) - 1;
                m &= m - 1;
                if (c == 2) {
                    // rank of (p0,p1) in lex combinations of 64 choose 2
                    idx = BASE2 + (p0 * (127 - p0)) / 2 + (p1 - p0 - 1);
                } else {
                    const int p2 = __ffsll((long long)m) - 1;
                    // #combos with first element < p0 = C(64,3) - C(64-p0,3)
                    const int r  = 64 - p0;
                    const int f  = C64_3 - (r * (r - 1) * (r - 2)) / 6;
                    // rank of (p1,p2) among remaining np = 63 - p0 positions
                    const int np = 63 - p0;
                    const int j  = p1 - p0 - 1;
                    const int k  = p2 - p0 - 1;
                    const int r2 = (j * (2 * np - 1 - j)) / 2 + (k - j - 1);
                    idx = BASE3 + f + r2;
                }
            }
        }
        out[gwarp] = W[idx] - g_lse;
    }
}

// ---------------------------------------------------------------------------
extern "C" void kernel_launch(void* const* d_in, const int* in_sizes, int n_in,
                              void* d_out, int out_size) {
    const int*   x = (const int*)d_in[0];      // (BATCH, 64) int32
    // d_in[1] = table (unused: index is computed combinatorially)
    const float* W = (const float*)d_in[2];    // (43745,) float32
    float*     out = (float*)d_out;            // (BATCH,) float32

    const int n_table = in_sizes[2];
    const int batch   = out_size;

    lse_kernel<<<1, 1024>>>(W, n_table);

    const int threads = 256;                   // 8 warps/block
    const int warps_needed = batch;
    const int blocks = (warps_needed * 32 + threads - 1) / threads;
    rank_gather_kernel<<<blocks, threads>>>(x, W, out, batch);
}

// round 2
// speedup vs baseline: 1.4706x; 1.4706x over previous
#include <cuda_runtime.h>
#include <cuda_bf16.h>
#include <math_constants.h>

// For each of 8192 batch rows (64 ints, 0/1, popcount<=3), the matching table
// row index is the combinatorial rank of the set-bit pattern (table = all
// popcount<=3 masks ordered by popcount then lexicographic). Output:
// W[idx] - logsumexp(W). Table input never read.

#define N_BITS   64
#define BASE1    1
#define BASE2    (1 + 64)
#define BASE3    (1 + 64 + 2016)
#define C64_3    41664

#define NPART    128                    // LSE partial blocks
#define ROWS_PER_WARP 4

// partials: .x = block max, .y = block sum of exp(W - max)
__device__ float2 g_part[NPART];

// ---------------------------------------------------------------------------
// Kernel 1: per-block partial (max, sumexp) over a contiguous chunk.
// chunk <= 512 guaranteed (43745/128 = 342), so <= 2 elements per thread.
// ---------------------------------------------------------------------------
__global__ void lse_part_kernel(const float* __restrict__ W, int n, int chunk) {
    __shared__ float sred[256];
    const int b = blockIdx.x;
    const int t = threadIdx.x;
    const int start = b * chunk;
    const int end   = min(start + chunk, n);

    const int i0 = start + t;
    const int i1 = start + t + 256;
    const bool h0 = (i0 < end);
    const bool h1 = (i1 < end);
    const float v0 = h0 ? W[i0] : -CUDART_INF_F;
    const float v1 = h1 ? W[i1] : -CUDART_INF_F;

    // block max (deterministic tree)
    sred[t] = fmaxf(v0, v1);
    __syncthreads();
    #pragma unroll
    for (int s = 128; s > 0; s >>= 1) {
        if (t < s) sred[t] = fmaxf(sred[t], sred[t + s]);
        __syncthreads();
    }
    const float m = sred[0];
    __syncthreads();

    // block sum of exp (deterministic tree)
    float acc = 0.0f;
    if (h0) acc += expf(v0 - m);
    if (h1) acc += expf(v1 - m);
    sred[t] = acc;
    __syncthreads();
    #pragma unroll
    for (int s = 128; s > 0; s >>= 1) {
        if (t < s) sred[t] += sred[t + s];
        __syncthreads();
    }
    if (t == 0) g_part[b] = make_float2(m, sred[0]);
}

// ---------------------------------------------------------------------------
// Kernel 2: per-block warp-0 prologue combines the 128 partials into lse
// (cheap, redundant per block -> no extra kernel / no grid sync). Then each
// warp ballots 4 rows into 64-bit masks, ranks, gathers.
// ---------------------------------------------------------------------------
__device__ __forceinline__ int rank_mask(unsigned long long m) {
    const int c = __popcll(m);
    if (c == 0) return 0;
    const int p0 = __ffsll((long long)m) - 1;
    m &= m - 1;
    if (c == 1) return BASE1 + p0;
    const int p1 = __ffsll((long long)m) - 1;
    m &= m - 1;
    if (c == 2) return BASE2 + (p0 * (127 - p0)) / 2 + (p1 - p0 - 1);
    const int p2 = __ffsll((long long)m) - 1;
    const int r  = 64 - p0;
    const int f  = C64_3 - (r * (r - 1) * (r - 2)) / 6;  // combos with first < p0
    const int np = 63 - p0;
    const int j  = p1 - p0 - 1;
    const int k  = p2 - p0 - 1;
    const int r2 = (j * (2 * np - 1 - j)) / 2 + (k - j - 1);
    return BASE3 + f + r2;
}

__global__ void rank_gather_kernel(const int* __restrict__ x,
                                   const float* __restrict__ W,
                                   float* __restrict__ out,
                                   int batch) {
    __shared__ float s_lse;
    const int t    = threadIdx.x;
    const int lane = t & 31;

    // ---- combine partials (warp 0 only) ----
    if (t < 32) {
        float2 p0 = g_part[lane];
        float2 p1 = g_part[lane + 32];
        float2 p2 = g_part[lane + 64];
        float2 p3 = g_part[lane + 96];
        float m = fmaxf(fmaxf(p0.x, p1.x), fmaxf(p2.x, p3.x));
        #pragma unroll
        for (int s = 16; s > 0; s >>= 1)
            m = fmaxf(m, __shfl_xor_sync(0xffffffffu, m, s));
        float acc = p0.y * expf(p0.x - m) + p1.y * expf(p1.x - m)
                  + p2.y * expf(p2.x - m) + p3.y * expf(p3.x - m);
        #pragma unroll
        for (int s = 16; s > 0; s >>= 1)
            acc += __shfl_xor_sync(0xffffffffu, acc, s);
        if (lane == 0) s_lse = m + logf(acc);
    }
    __syncthreads();
    const float lse = s_lse;

    // ---- 4 rows per warp ----
    const int warp = blockIdx.x * (blockDim.x >> 5) + (t >> 5);
    const int base = warp * ROWS_PER_WARP;
    if (base >= batch) return;

    const int* p = x + (long long)base * N_BITS;
    // 8 coalesced 128B loads, front-batched for MLP
    const int a0 = p[lane];        const int b0 = p[32  + lane];
    const int a1 = p[64  + lane];  const int b1 = p[96  + lane];
    const int a2 = p[128 + lane];  const int b2 = p[160 + lane];
    const int a3 = p[192 + lane];  const int b3 = p[224 + lane];

    const unsigned lo0 = __ballot_sync(0xffffffffu, a0 != 0);
    const unsigned hi0 = __ballot_sync(0xffffffffu, b0 != 0);
    const unsigned lo1 = __ballot_sync(0xffffffffu, a1 != 0);
    const unsigned hi1 = __ballot_sync(0xffffffffu, b1 != 0);
    const unsigned lo2 = __ballot_sync(0xffffffffu, a2 != 0);
    const unsigned hi2 = __ballot_sync(0xffffffffu, b2 != 0);
    const unsigned lo3 = __ballot_sync(0xffffffffu, a3 != 0);
    const unsigned hi3 = __ballot_sync(0xffffffffu, b3 != 0);

    if (lane < ROWS_PER_WARP) {
        unsigned lo = (lane == 0) ? lo0 : (lane == 1) ? lo1 : (lane == 2) ? lo2 : lo3;
        unsigned hi = (lane == 0) ? hi0 : (lane == 1) ? hi1 : (lane == 2) ? hi2 : hi3;
        const unsigned long long m =
            (unsigned long long)lo | ((unsigned long long)hi << 32);
        const int idx = rank_mask(m);
        out[base + lane] = W[idx] - lse;
    }
}

// ---------------------------------------------------------------------------
extern "C" void kernel_launch(void* const* d_in, const int* in_sizes, int n_in,
                              void* d_out, int out_size) {
    const int*   x = (const int*)d_in[0];      // (BATCH, 64) int32
    const float* W = (const float*)d_in[2];    // (43745,) float32
    float*     out = (float*)d_out;            // (BATCH,) float32

    const int n_table = in_sizes[2];
    const int batch   = out_size;
    const int chunk   = (n_table + NPART - 1) / NPART;   // 342 for 43745

    lse_part_kernel<<<NPART, 256>>>(W, n_table, chunk);

    const int warps_per_block = 8;            // 256 threads
    const int rows_per_block  = warps_per_block * ROWS_PER_WARP;
    const int blocks = (batch + rows_per_block - 1) / rows_per_block;  // 256
    rank_gather_kernel<<<blocks, 256>>>(x, W, out, batch);
}

// round 4
// speedup vs baseline: 1.4760x; 1.0037x over previous
#include <cuda_runtime.h>
#include <cuda_bf16.h>
#include <math_constants.h>

// Single fused kernel. Table row index = combinatorial rank of the <=3 set
// bits (table = all popcount<=3 masks of 64 bits, ordered by popcount then
// lexicographic). out[b] = W[rank(x_b)] - logsumexp(W). Table input unread.
//
// Grid = 128 blocks (<= 148 SMs -> all co-resident), software barrier via a
// monotonically increasing arrival counter (epoch-based, no reset needed;
// graph replays are stream-serialized so epochs never interleave). All
// reductions are fixed-order -> deterministic.

#define N_BITS   64
#define BASE1    1
#define BASE2    (1 + 64)
#define BASE3    (1 + 64 + 2016)
#define C64_3    41664

#define NBLK          128
#define THREADS       256
#define ROWS_PER_WARP 8      // 8 warps * 8 rows = 64 rows/block * 128 = 8192

__device__ float2   g_part[NBLK];   // per-block (max, sumexp)
__device__ unsigned g_cnt;          // monotonic arrival counter (zero-init)

__device__ __forceinline__ int rank_mask(unsigned long long m) {
    const int c = __popcll(m);
    if (c == 0) return 0;
    const int p0 = __ffsll((long long)m) - 1;
    m &= m - 1;
    if (c == 1) return BASE1 + p0;
    const int p1 = __ffsll((long long)m) - 1;
    m &= m - 1;
    if (c == 2) return BASE2 + (p0 * (127 - p0)) / 2 + (p1 - p0 - 1);
    const int p2 = __ffsll((long long)m) - 1;
    const int r  = 64 - p0;
    const int f  = C64_3 - (r * (r - 1) * (r - 2)) / 6;  // combos with first < p0
    const int np = 63 - p0;
    const int j  = p1 - p0 - 1;
    const int k  = p2 - p0 - 1;
    const int r2 = (j * (2 * np - 1 - j)) / 2 + (k - j - 1);
    return BASE3 + f + r2;
}

__global__ void __launch_bounds__(THREADS)
fused_kernel(const int* __restrict__ x,
             const float* __restrict__ W,
             float* __restrict__ out,
             int n_table, int batch, int chunk) {
    __shared__ float sred[THREADS];
    __shared__ float s_lse;

    const int b    = blockIdx.x;
    const int t    = threadIdx.x;
    const int lane = t & 31;
    const int warp = t >> 5;

    // ---------------- front-issue x loads (16 coalesced 128B lines/warp) ----
    const int row0 = b * (8 * ROWS_PER_WARP) + warp * ROWS_PER_WARP;
    const int* p = x + (long long)row0 * N_BITS;
    int a[2 * ROWS_PER_WARP];
    #pragma unroll
    for (int i = 0; i < 2 * ROWS_PER_WARP; i++)
        a[i] = p[i * 32 + lane];

    // ---------------- this block's LSE partial over W[start:start+chunk) ----
    const int start = b * chunk;
    const int end   = min(start + chunk, n_table);
    const int i0 = start + t;
    const int i1 = start + t + THREADS;
    const bool h0 = (i0 < end);
    const bool h1 = (i1 < end);
    const float v0 = h0 ? W[i0] : -CUDART_INF_F;
    const float v1 = h1 ? W[i1] : -CUDART_INF_F;

    sred[t] = fmaxf(v0, v1);
    __syncthreads();
    #pragma unroll
    for (int s = THREADS / 2; s > 0; s >>= 1) {
        if (t < s) sred[t] = fmaxf(sred[t], sred[t + s]);
        __syncthreads();
    }
    const float bm = sred[0];
    __syncthreads();

    float acc = 0.0f;
    if (h0) acc += expf(v0 - bm);
    if (h1) acc += expf(v1 - bm);
    sred[t] = acc;
    __syncthreads();
    #pragma unroll
    for (int s = THREADS / 2; s > 0; s >>= 1) {
        if (t < s) sred[t] += sred[t + s];
        __syncthreads();
    }
    if (t == 0) g_part[b] = make_float2(bm, sred[0]);

    // ---------------- ballots -> rank -> issue W gathers (pre-barrier) ------
    // All ballots executed by the full warp (convergent).
    unsigned bal[2 * ROWS_PER_WARP];
    #pragma unroll
    for (int i = 0; i < 2 * ROWS_PER_WARP; i++)
        bal[i] = __ballot_sync(0xffffffffu, a[i] != 0);

    // bal[] is warp-uniform; lane r picks its own pair with predicated moves
    // (no warp collectives under divergence).
    unsigned lo = 0, hi = 0;
    #pragma unroll
    for (int r = 0; r < ROWS_PER_WARP; r++) {
        if (lane == r) { lo = bal[2 * r]; hi = bal[2 * r + 1]; }
    }

    float wv = 0.0f;
    int   myrow = -1;
    if (lane < ROWS_PER_WARP) {
        const unsigned long long mask =
            (unsigned long long)lo | ((unsigned long long)hi << 32);
        const int idx = rank_mask(mask);
        myrow = row0 + lane;
        if (myrow < batch) wv = W[idx];   // gather issued before the barrier
    }

    // ---------------- global arrive + spin (epoch counter, no reset) --------
    __syncthreads();                       // g_part[b] store complete
    if (t == 0) {
        __threadfence();
        const unsigned old    = atomicAdd(&g_cnt, 1u);
        const unsigned target = (old / NBLK + 1u) * NBLK;
        while (*((volatile unsigned*)&g_cnt) < target) __nanosleep(32);
        __threadfence();
    }
    __syncthreads();

    // ---------------- combine 128 partials (warp 0), broadcast --------------
    if (t < 32) {
        float2 q0 = g_part[lane];
        float2 q1 = g_part[lane + 32];
        float2 q2 = g_part[lane + 64];
        float2 q3 = g_part[lane + 96];
        float m = fmaxf(fmaxf(q0.x, q1.x), fmaxf(q2.x, q3.x));
        #pragma unroll
        for (int s = 16; s > 0; s >>= 1)
            m = fmaxf(m, __shfl_xor_sync(0xffffffffu, m, s));
        float sum = q0.y * expf(q0.x - m) + q1.y * expf(q1.x - m)
                  + q2.y * expf(q2.x - m) + q3.y * expf(q3.x - m);
        #pragma unroll
        for (int s = 16; s > 0; s >>= 1)
            sum += __shfl_xor_sync(0xffffffffu, sum, s);
        if (lane == 0) s_lse = m + logf(sum);
    }
    __syncthreads();
    const float lse = s_lse;

    // ---------------- write out ---------------------------------------------
    if (lane < ROWS_PER_WARP && myrow >= 0 && myrow < batch)
        out[myrow] = wv - lse;
}

// ---------------------------------------------------------------------------
extern "C" void kernel_launch(void* const* d_in, const int* in_sizes, int n_in,
                              void* d_out, int out_size) {
    const int*   x = (const int*)d_in[0];      // (BATCH, 64) int32
    const float* W = (const float*)d_in[2];    // (43745,) float32
    float*     out = (float*)d_out;            // (BATCH,) float32

    const int n_table = in_sizes[2];
    const int batch   = out_size;
    const int chunk   = (n_table + NBLK - 1) / NBLK;   // 342

    fused_kernel<<<NBLK, THREADS>>>(x, W, out, n_table, batch, chunk);
}